// round 10
// baseline (speedup 1.0000x reference)
#include <cuda_runtime.h>

// Integrate-and-fire: per neuron (b,h,w,c), scan t: v += x; if (v > 2) {spike=1; v=0}
// Two independent 100-step windows (v resets at t==100) -> chunk parallelism.
//
// Topology (best warm-loop class): 1024 threads, tile 4w x 32h x 8c, scalar
// U=5, 2 blocks/SM (~80% occupancy, single wave).
//   input : warp = fixed h, lane = wl*8+c -> full 128B line
//   output: warp = fixed (w,c), lane = h  -> full 128B line
// Float smem transpose, pitch 33 (33 ⊥ 32: both the lane-stride-1 write and
// the lane-stride-33 read are bank-conflict-free). Ping-pong phases: ONE
// barrier per batch, no register copies.
//
// This round: FULLY UNROLLED batch pipeline (10 batches) — every global and
// shared address is an immediate offset off a single base register; zero
// steady-state integer address math. I-footprint ~6KB (~L0-resident).
//
// Input  index: b*6553600 + t*32768 + h*512 + w*8 + c
// Output index: b*6553600 + t*32768 + w*512 + c*64 + h

#define T_CHUNK  100
#define STRIDE_T 32768      // 64*64*8
#define STRIDE_B 6553600    // 200*STRIDE_T
#define VM_THR   2.0f
#define U        5          // batch depth; T_CHUNK/U = 20 batches? no: 10 per phase pair
#define NBATCH   (T_CHUNK / U)   // 20 batches of 5 -> wait: 100/5 = 20

__global__ __launch_bounds__(1024, 2)
void iaf_kernel(const float* __restrict__ in, float* __restrict__ out) {
    const int wt    = blockIdx.x >> 1;   // 0..15  (w tile of 4)
    const int hh    = blockIdx.x & 1;    // 0..1   (h half of 32)
    const int b     = blockIdx.y;        // 0..3
    const int chunk = blockIdx.z;        // 0..1
    const int tid   = threadIdx.x;       // 0..1023

    __shared__ float s[2][U][32 * 33];

    const size_t base = (size_t)b * STRIDE_B + (size_t)chunk * T_CHUNK * STRIDE_T;

    // input role: hl = h within half (warp id), lane = wl*8+c
    const int hl   = tid >> 5;
    const int lane = tid & 31;
    const float* ip = in + base + (size_t)(hh * 32 + hl) * 512 + wt * 32 + lane;

    // output role: wc_o = wl'*8+c' (warp id), lane = h within half
    const int wc_o = tid >> 5;
    float* op = out + base + (size_t)wt * 2048
              + (wc_o >> 3) * 512 + (wc_o & 7) * 64 + hh * 32 + lane;

    const int swr = hl * 33 + lane;      // write slot (lane stride 1)
    const int srd = lane * 33 + wc_o;    // read slot  (lane stride 33)

    float reg[2][U];
    #pragma unroll
    for (int k = 0; k < U; k++) reg[0][k] = ip[k * STRIDE_T];   // prime phase 0

    float v = 0.0f;

    // Fully unrolled: bt = batch index 0..19, phase = bt & 1. All offsets are
    // compile-time constants -> pure immediate-offset LDG/STS/LDS/STG.
    #pragma unroll
    for (int bt = 0; bt < NBATCH; ++bt) {
        const int ph = bt & 1;
        const int tb = bt * U;
        // prefetch next batch into the other phase (no register copies)
        if (bt + 1 < NBATCH) {
            #pragma unroll
            for (int k = 0; k < U; k++)
                reg[ph ^ 1][k] = ip[(tb + U + k) * STRIDE_T];
        }
        // sequential integrate-and-fire; spikes -> smem floats
        #pragma unroll
        for (int k = 0; k < U; k++) {
            v += reg[ph][k];
            float sp = 0.0f;
            if (v > VM_THR) { sp = 1.0f; v = 0.0f; }
            s[ph][k][swr] = sp;
        }
        __syncthreads();   // orders writes(ph) before reads(ph); next write to
                           // this phase is 2 batches away, always separated
                           // from these reads by a later barrier
        // fully-coalesced 128B streaming stores through the transposed role
        #pragma unroll
        for (int k = 0; k < U; k++)
            __stcs(op + (tb + k) * STRIDE_T, s[ph][k][srd]);
    }
}

extern "C" void kernel_launch(void* const* d_in, const int* in_sizes, int n_in,
                              void* d_out, int out_size) {
    const float* in = (const float*)d_in[0];
    float* out = (float*)d_out;
    dim3 grid(32, 4, 2);   // (wt*2+hh, b, chunk)
    iaf_kernel<<<grid, 1024>>>(in, out);
}